// round 11
// baseline (speedup 1.0000x reference)
#include <cuda_runtime.h>

#define Bn 2
#define H 384
#define W 1280
#define HW (H * W)
#define BHW (Bn * H * W)

// Fused-tile geometry: each block produces OH x OW outputs for 2 Jacobi steps.
#define OW 128
#define OH 8
#define MW (OW + 2)   // pass-1 (mid) region
#define MH (OH + 2)
#define IW (OW + 4)   // input region
#define IH (OH + 4)

// Persistent scratch (no allocations allowed in kernel_launch).
__device__ float g_w8[(size_t)8 * BHW];  // pixel-major interleaved weights: [pix][k0..k7]
__device__ float g_c[BHW];               // constant term per pixel
__device__ float g_d0[BHW];              // ping
__device__ float g_d1[BHW];              // pong

// Neighbor offsets per channel k (derived from PADS):
// k0:(+1,+1) k1:(+1,0) k2:(+1,-1) k3:(0,+1) k4:(0,-1) k5:(-1,+1) k6:(-1,0) k7:(-1,-1)
__constant__ int c_di[8] = { 1, 1, 1, 0, 0, -1, -1, -1 };
__constant__ int c_dj[8] = { 1, 0, -1, 1, -1, 1, 0, -1 };

__global__ void prep_kernel(const float* __restrict__ guid,
                            const float* __restrict__ blur,
                            const float* __restrict__ sparse) {
    int idx = blockIdx.x * blockDim.x + threadIdx.x;
    if (idx >= BHW) return;
    int j = idx % W;
    int t = idx / W;
    int i = t % H;
    int b = t / H;

    float v[8];
    float den = 0.0f;
#pragma unroll
    for (int k = 0; k < 8; k++) {
        int ni = i + c_di[k];
        int nj = j + c_dj[k];
        float val = 0.0f;
        if (ni >= 0 && ni < H && nj >= 0 && nj < W)
            val = guid[((b * 8 + k) * H + ni) * W + nj];
        v[k] = val;
        den += fabsf(val);
    }
    float inv = 1.0f / (den + 1e-9f);
    float gs = 0.0f;
#pragma unroll
    for (int k = 0; k < 8; k++) {
        v[k] *= inv;
        gs += v[k];
    }
    float m = (sparse[idx] > 0.0f) ? 1.0f : 0.0f;
    float fac = 1.0f - m;
    float raw = blur[idx];
    g_c[idx] = (fac * (1.0f - gs) + m) * raw;

    float4 lo = make_float4(fac * v[0], fac * v[1], fac * v[2], fac * v[3]);
    float4 hi = make_float4(fac * v[4], fac * v[5], fac * v[6], fac * v[7]);
    *reinterpret_cast<float4*>(g_w8 + (size_t)idx * 8)     = lo;
    *reinterpret_cast<float4*>(g_w8 + (size_t)idx * 8 + 4) = hi;
}

__device__ __forceinline__ float stencil8(const float* __restrict__ wb,
                                          const float* __restrict__ cb,
                                          int pidx,
                                          const float* s, int stride, int r, int c) {
    // s is the source tile; pixel sits at s[(r)*stride + c] with a 1-cell halo
    // around it (caller passes r,c of the TOP-LEFT neighbor position + 0 base).
    float4 w0 = *reinterpret_cast<const float4*>(wb + (size_t)pidx * 8);
    float4 w1 = *reinterpret_cast<const float4*>(wb + (size_t)pidx * 8 + 4);
    const float* up  = s + (r    ) * stride + c;   // row above
    const float* mid = s + (r + 1) * stride + c;   // own row
    const float* dn  = s + (r + 2) * stride + c;   // row below
    float acc = cb[pidx];
    acc = fmaf(w0.x, dn[2],  acc);   // (+1,+1)
    acc = fmaf(w0.y, dn[1],  acc);   // (+1, 0)
    acc = fmaf(w0.z, dn[0],  acc);   // (+1,-1)
    acc = fmaf(w0.w, mid[2], acc);   // ( 0,+1)
    acc = fmaf(w1.x, mid[0], acc);   // ( 0,-1)
    acc = fmaf(w1.y, up[2],  acc);   // (-1,+1)
    acc = fmaf(w1.z, up[1],  acc);   // (-1, 0)
    acc = fmaf(w1.w, up[0],  acc);   // (-1,-1)
    return acc;
}

// Two fused Jacobi sweeps per launch via shared-memory temporal blocking.
__global__ __launch_bounds__(256) void prop2_kernel(const float* __restrict__ src,
                                                    float* __restrict__ dst) {
    __shared__ float s_in[IH * IW];
    __shared__ float s_mid[MH * MW];

    const int tx = threadIdx.x;
    const int tj = blockIdx.x * OW;     // tile origin (output space)
    const int ti = blockIdx.y * OH;
    const int b  = blockIdx.z;

    const float* plane = src + (size_t)b * HW;
    const float* wb = g_w8 + (size_t)b * HW * 8;
    const float* cb = g_c  + (size_t)b * HW;

    // ---- load input tile: global rows [ti-2, ti+OH+1], cols [tj-2, tj+OW+1]
    // Clamped loads: clamped cells are only ever multiplied by exactly-zero
    // weights (OOB neighbors have w==0 by construction in prep_kernel).
    for (int idx = tx; idx < IH * IW; idx += 256) {
        int r = idx / IW, c = idx % IW;
        int gi = min(max(ti - 2 + r, 0), H - 1);
        int gj = min(max(tj - 2 + c, 0), W - 1);
        s_in[idx] = plane[gi * W + gj];
    }
    __syncthreads();

    // ---- pass 1: mid region, global rows [ti-1, ti+OH], cols [tj-1, tj+OW]
    // Mid pixels outside the image compute a finite (garbage) value using the
    // clamped pixel's weights; pass 2 consumes them only with zero weight.
    for (int idx = tx; idx < MH * MW; idx += 256) {
        int r = idx / MW, c = idx % MW;
        int gi = min(max(ti - 1 + r, 0), H - 1);
        int gj = min(max(tj - 1 + c, 0), W - 1);
        // mid pixel sits at s_in[(r+1)*IW + (c+1)]; pass top-left base (r, c)
        s_mid[idx] = stencil8(wb, cb, gi * W + gj, s_in, IW, r, c);
    }
    __syncthreads();

    // ---- pass 2: output region OH x OW (always fully inside the image).
    // Weight re-reads hit L1 (41.6 KB tile footprint << 228 KB L1).
    for (int idx = tx; idx < OH * OW; idx += 256) {
        int r = idx / OW, c = idx % OW;
        int gi = ti + r, gj = tj + c;
        float v = stencil8(wb, cb, gi * W + gj, s_mid, MW, r, c);
        dst[(size_t)b * HW + gi * W + gj] = v;
    }
}

extern "C" void kernel_launch(void* const* d_in, const int* in_sizes, int n_in,
                              void* d_out, int out_size) {
    const float* guid   = (const float*)d_in[0];   // (B, 8, H, W)
    const float* blur   = (const float*)d_in[1];   // (B, 1, H, W)
    const float* sparse = (const float*)d_in[2];   // (B, 1, H, W)
    float* out = (float*)d_out;                    // (B, H, W)

    const int PROP_TIME = 24;                      // fixed by setup_inputs
    const int N_FUSED = PROP_TIME / 2;             // 12 launches of 2 sweeps

    prep_kernel<<<(BHW + 255) / 256, 256>>>(guid, blur, sparse);

    float* dbuf[2];
    cudaGetSymbolAddress((void**)&dbuf[0], g_d0);
    cudaGetSymbolAddress((void**)&dbuf[1], g_d1);

    dim3 block(256, 1, 1);
    dim3 grid(W / OW, H / OH, Bn);                 // (10, 48, 2)

    const float* src = blur;
    for (int t = 1; t <= N_FUSED; t++) {
        float* dst = (t == N_FUSED) ? out : dbuf[t & 1];
        prop2_kernel<<<grid, block>>>(src, dst);
        src = dst;
    }
}

// round 13
// speedup vs baseline: 1.1742x; 1.1742x over previous
#include <cuda_runtime.h>
#include <cuda_fp16.h>

#define Bn 2
#define H 384
#define W 1280
#define HW (H * W)
#define BHW (Bn * H * W)

// Persistent scratch (no allocations allowed in kernel_launch).
__device__ __half g_wh[(size_t)8 * BHW];  // fp16 weights, pixel-major [pix][k0..k7] (16B/px)
__device__ float  g_c[BHW];               // constant term per pixel (fp32)
__device__ float  g_d0[BHW];              // ping
__device__ float  g_d1[BHW];              // pong

// Neighbor offsets per channel k (derived from PADS):
// k0:(+1,+1) k1:(+1,0) k2:(+1,-1) k3:(0,+1) k4:(0,-1) k5:(-1,+1) k6:(-1,0) k7:(-1,-1)
__constant__ int c_di[8] = { 1, 1, 1, 0, 0, -1, -1, -1 };
__constant__ int c_dj[8] = { 1, 0, -1, 1, -1, 1, 0, -1 };

__global__ void prep_kernel(const float* __restrict__ guid,
                            const float* __restrict__ blur,
                            const float* __restrict__ sparse) {
    int idx = blockIdx.x * blockDim.x + threadIdx.x;
    if (idx >= BHW) return;
    int j = idx % W;
    int t = idx / W;
    int i = t % H;
    int b = t / H;

    float v[8];
    float den = 0.0f;
#pragma unroll
    for (int k = 0; k < 8; k++) {
        int ni = i + c_di[k];
        int nj = j + c_dj[k];
        float val = 0.0f;
        if (ni >= 0 && ni < H && nj >= 0 && nj < W)
            val = guid[((b * 8 + k) * H + ni) * W + nj];
        v[k] = val;
        den += fabsf(val);
    }
    float inv = 1.0f / (den + 1e-9f);
    float gs = 0.0f;
#pragma unroll
    for (int k = 0; k < 8; k++) {
        v[k] *= inv;
        gs += v[k];
    }
    float m = (sparse[idx] > 0.0f) ? 1.0f : 0.0f;
    float fac = 1.0f - m;
    float raw = blur[idx];
    g_c[idx] = (fac * (1.0f - gs) + m) * raw;

    // Pack 8 fp16 weights per pixel (16B, aligned). OOB weights are exactly 0.
    __half2 h0 = __floats2half2_rn(fac * v[0], fac * v[1]);
    __half2 h1 = __floats2half2_rn(fac * v[2], fac * v[3]);
    __half2 h2 = __floats2half2_rn(fac * v[4], fac * v[5]);
    __half2 h3 = __floats2half2_rn(fac * v[6], fac * v[7]);
    uint4 pack;
    pack.x = *reinterpret_cast<unsigned int*>(&h0);
    pack.y = *reinterpret_cast<unsigned int*>(&h1);
    pack.z = *reinterpret_cast<unsigned int*>(&h2);
    pack.w = *reinterpret_cast<unsigned int*>(&h3);
    *reinterpret_cast<uint4*>(g_wh + (size_t)idx * 8) = pack;
}

// Load 6 consecutive d values [j0-1 .. j0+4] from one row (clamped at edges;
// the clamped values are always multiplied by an exactly-zero weight).
__device__ __forceinline__ void load_row6(const float* __restrict__ row, int j0, float v[6]) {
    v[0] = row[(j0 > 0) ? (j0 - 1) : 0];
    float4 mid = *reinterpret_cast<const float4*>(row + j0);
    v[1] = mid.x; v[2] = mid.y; v[3] = mid.z; v[4] = mid.w;
    v[5] = row[(j0 + 4 < W) ? (j0 + 4) : (W - 1)];
}

// One Jacobi sweep: d_new = C + sum_k w'_k * d[nbr_k].  4 pixels per thread.
__global__ __launch_bounds__(256) void prop_kernel(const float* __restrict__ src,
                                                   float* __restrict__ dst) {
    int j0 = (blockIdx.x * blockDim.x + threadIdx.x) * 4;   // W=1280 = 10 blocks * 32 lanes * 4
    int i  = blockIdx.y * blockDim.y + threadIdx.y;         // H=384  = 48 blocks * 8
    int b  = blockIdx.z;
    int base = (b * H + i) * W + j0;

    const float* plane = src + (size_t)b * HW;
    int iu = (i > 0) ? (i - 1) : 0;
    int id = (i + 1 < H) ? (i + 1) : (H - 1);

    float ru[6], rm[6], rd[6];
    load_row6(plane + iu * W, j0, ru);
    load_row6(plane + i  * W, j0, rm);
    load_row6(plane + id * W, j0, rd);

    float4 c4 = *reinterpret_cast<const float4*>(g_c + base);
    float c[4] = { c4.x, c4.y, c4.z, c4.w };

    float o[4];
#pragma unroll
    for (int p = 0; p < 4; p++) {
        uint4 wv = *reinterpret_cast<const uint4*>(g_wh + (size_t)(base + p) * 8);
        __half2 h0 = *reinterpret_cast<__half2*>(&wv.x);
        __half2 h1 = *reinterpret_cast<__half2*>(&wv.y);
        __half2 h2 = *reinterpret_cast<__half2*>(&wv.z);
        __half2 h3 = *reinterpret_cast<__half2*>(&wv.w);
        float2 w01 = __half22float2(h0);   // k0, k1
        float2 w23 = __half22float2(h1);   // k2, k3
        float2 w45 = __half22float2(h2);   // k4, k5
        float2 w67 = __half22float2(h3);   // k6, k7

        float acc = c[p];
        acc = fmaf(w01.x, rd[p + 2], acc);   // (+1,+1)
        acc = fmaf(w01.y, rd[p + 1], acc);   // (+1, 0)
        acc = fmaf(w23.x, rd[p],     acc);   // (+1,-1)
        acc = fmaf(w23.y, rm[p + 2], acc);   // ( 0,+1)
        acc = fmaf(w45.x, rm[p],     acc);   // ( 0,-1)
        acc = fmaf(w45.y, ru[p + 2], acc);   // (-1,+1)
        acc = fmaf(w67.x, ru[p + 1], acc);   // (-1, 0)
        acc = fmaf(w67.y, ru[p],     acc);   // (-1,-1)
        o[p] = acc;
    }
    *reinterpret_cast<float4*>(dst + base) = make_float4(o[0], o[1], o[2], o[3]);
}

extern "C" void kernel_launch(void* const* d_in, const int* in_sizes, int n_in,
                              void* d_out, int out_size) {
    const float* guid   = (const float*)d_in[0];   // (B, 8, H, W)
    const float* blur   = (const float*)d_in[1];   // (B, 1, H, W)
    const float* sparse = (const float*)d_in[2];   // (B, 1, H, W)
    float* out = (float*)d_out;                    // (B, H, W)

    const int PROP_TIME = 24;                      // fixed by setup_inputs

    prep_kernel<<<(BHW + 255) / 256, 256>>>(guid, blur, sparse);

    float* dbuf[2];
    cudaGetSymbolAddress((void**)&dbuf[0], g_d0);
    cudaGetSymbolAddress((void**)&dbuf[1], g_d1);

    dim3 block(32, 8, 1);
    dim3 grid(W / (32 * 4), H / 8, Bn);            // (10, 48, 2)

    const float* src = blur;
    for (int t = 1; t <= PROP_TIME; t++) {
        float* dst = (t == PROP_TIME) ? out : dbuf[t & 1];
        prop_kernel<<<grid, block>>>(src, dst);
        src = dst;
    }
}

// round 14
// speedup vs baseline: 1.4139x; 1.2041x over previous
#include <cuda_runtime.h>
#include <cuda_fp16.h>

#define Bn 2
#define H 384
#define W 1280
#define HW (H * W)
#define BHW (Bn * H * W)

// Persistent-kernel tiling: 128 blocks (2 x 32 x 2), tile = 640 x 12 px.
#define TW 640
#define TH 12
#define SPR (TW / 4)            // strips per row = 160
#define NSTRIP (SPR * TH)       // 1920 strips per tile
#define THREADS 960             // 2 strips per thread
#define NBLK ((W / TW) * (H / TH) * Bn)   // 128
#define ITERS 24
#define SMEM_BYTES (NSTRIP * 4 * 16 + NSTRIP * 4 * 4)   // w: 122880 + c: 30720 = 153600

// Persistent scratch (no allocations allowed in kernel_launch).
__device__ __half   g_wh[(size_t)8 * BHW];  // fp16 weights, pixel-major [pix][k0..k7]
__device__ float    g_c[BHW];               // constant term per pixel
__device__ float    g_d0[BHW];              // ping
__device__ float    g_d1[BHW];              // pong
__device__ unsigned g_bar;                  // grid barrier counter (reset by prep)

// Neighbor offsets per channel k (derived from PADS):
// k0:(+1,+1) k1:(+1,0) k2:(+1,-1) k3:(0,+1) k4:(0,-1) k5:(-1,+1) k6:(-1,0) k7:(-1,-1)
__constant__ int c_di[8] = { 1, 1, 1, 0, 0, -1, -1, -1 };
__constant__ int c_dj[8] = { 1, 0, -1, 1, -1, 1, 0, -1 };

__global__ void prep_kernel(const float* __restrict__ guid,
                            const float* __restrict__ blur,
                            const float* __restrict__ sparse) {
    int idx = blockIdx.x * blockDim.x + threadIdx.x;
    if (idx == 0) g_bar = 0;                 // reset grid barrier every call
    if (idx >= BHW) return;
    int j = idx % W;
    int t = idx / W;
    int i = t % H;
    int b = t / H;

    float v[8];
    float den = 0.0f;
#pragma unroll
    for (int k = 0; k < 8; k++) {
        int ni = i + c_di[k];
        int nj = j + c_dj[k];
        float val = 0.0f;
        if (ni >= 0 && ni < H && nj >= 0 && nj < W)
            val = guid[((b * 8 + k) * H + ni) * W + nj];
        v[k] = val;
        den += fabsf(val);
    }
    float inv = 1.0f / (den + 1e-9f);
    float gs = 0.0f;
#pragma unroll
    for (int k = 0; k < 8; k++) {
        v[k] *= inv;
        gs += v[k];
    }
    float m = (sparse[idx] > 0.0f) ? 1.0f : 0.0f;
    float fac = 1.0f - m;
    float raw = blur[idx];
    g_c[idx] = (fac * (1.0f - gs) + m) * raw;

    // Pack 8 fp16 weights per pixel (16B). OOB weights are exactly 0 in fp16 too.
    __half2 h0 = __floats2half2_rn(fac * v[0], fac * v[1]);
    __half2 h1 = __floats2half2_rn(fac * v[2], fac * v[3]);
    __half2 h2 = __floats2half2_rn(fac * v[4], fac * v[5]);
    __half2 h3 = __floats2half2_rn(fac * v[6], fac * v[7]);
    uint4 pack;
    pack.x = *reinterpret_cast<unsigned int*>(&h0);
    pack.y = *reinterpret_cast<unsigned int*>(&h1);
    pack.z = *reinterpret_cast<unsigned int*>(&h2);
    pack.w = *reinterpret_cast<unsigned int*>(&h3);
    *reinterpret_cast<uint4*>(g_wh + (size_t)idx * 8) = pack;
}

// Load 6 consecutive d values [j0-1 .. j0+4] from one row (clamped at image edges;
// clamped values are always multiplied by an exactly-zero weight).
__device__ __forceinline__ void load_row6(const float* __restrict__ row, int j0, float v[6]) {
    v[0] = row[(j0 > 0) ? (j0 - 1) : 0];
    float4 mid = *reinterpret_cast<const float4*>(row + j0);
    v[1] = mid.x; v[2] = mid.y; v[3] = mid.z; v[4] = mid.w;
    v[5] = row[(j0 + 4 < W) ? (j0 + 4) : (W - 1)];
}

// Persistent kernel: all 24 Jacobi sweeps in ONE launch.
// Weights + C live in SMEM for the whole kernel; d ping-pongs through L2.
// Grid-wide sync via release/acquire spin barrier (all 128 blocks co-resident:
// 153.6KB smem forces 1 block/SM, and 128 < 148 SMs).
__global__ __launch_bounds__(THREADS, 1)
void prop_persist(const float* __restrict__ d_init, float* __restrict__ out) {
    extern __shared__ char smem_raw[];
    uint4* s_w = reinterpret_cast<uint4*>(smem_raw);                       // [p][strip]
    float* s_c = reinterpret_cast<float*>(smem_raw + NSTRIP * 4 * 16);     // [p][strip]

    const int bx = blockIdx.x;       // 0..1   (640-wide halves)
    const int by = blockIdx.y;       // 0..31  (12-row bands)
    const int b  = blockIdx.z;       // batch
    const int ti = by * TH;
    const int tj = bx * TW;
    const int tid = threadIdx.x;

    // ---- prologue: stage this tile's weights + C into smem (transposed so
    // that per-strip LDS is lane-contiguous -> conflict-free).
    for (int idx = tid; idx < TH * TW; idx += THREADS) {
        int r = idx / TW, c = idx - r * TW;
        int strip = r * SPR + (c >> 2);
        int p = c & 3;
        int gp = (b * H + ti + r) * W + tj + c;
        s_w[p * NSTRIP + strip] = *reinterpret_cast<const uint4*>(g_wh + (size_t)gp * 8);
        s_c[p * NSTRIP + strip] = g_c[gp];
    }
    __syncthreads();

    const float* src = d_init;
    for (int it = 1; it <= ITERS; ++it) {
        float* dst = (it == ITERS) ? out : ((it & 1) ? g_d1 : g_d0);
        const float* plane = src + (size_t)b * HW;
        float* dplane = dst + (size_t)b * HW;

#pragma unroll
        for (int k = 0; k < 2; ++k) {
            int st = tid + k * THREADS;          // strip id in [0, 1920)
            int r  = st / SPR;
            int cq = st - r * SPR;
            int gi = ti + r;
            int j0 = tj + cq * 4;
            int iu = (gi > 0) ? (gi - 1) : 0;
            int id = (gi + 1 < H) ? (gi + 1) : (H - 1);

            float ru[6], rm[6], rd[6];
            load_row6(plane + iu * W, j0, ru);
            load_row6(plane + gi * W, j0, rm);
            load_row6(plane + id * W, j0, rd);

            float o[4];
#pragma unroll
            for (int p = 0; p < 4; p++) {
                uint4 wv = s_w[p * NSTRIP + st];
                __half2 h0 = *reinterpret_cast<__half2*>(&wv.x);
                __half2 h1 = *reinterpret_cast<__half2*>(&wv.y);
                __half2 h2 = *reinterpret_cast<__half2*>(&wv.z);
                __half2 h3 = *reinterpret_cast<__half2*>(&wv.w);
                float2 w01 = __half22float2(h0);   // k0, k1
                float2 w23 = __half22float2(h1);   // k2, k3
                float2 w45 = __half22float2(h2);   // k4, k5
                float2 w67 = __half22float2(h3);   // k6, k7

                float acc = s_c[p * NSTRIP + st];
                acc = fmaf(w01.x, rd[p + 2], acc);   // (+1,+1)
                acc = fmaf(w01.y, rd[p + 1], acc);   // (+1, 0)
                acc = fmaf(w23.x, rd[p],     acc);   // (+1,-1)
                acc = fmaf(w23.y, rm[p + 2], acc);   // ( 0,+1)
                acc = fmaf(w45.x, rm[p],     acc);   // ( 0,-1)
                acc = fmaf(w45.y, ru[p + 2], acc);   // (-1,+1)
                acc = fmaf(w67.x, ru[p + 1], acc);   // (-1, 0)
                acc = fmaf(w67.y, ru[p],     acc);   // (-1,-1)
                o[p] = acc;
            }
            *reinterpret_cast<float4*>(dplane + gi * W + j0) =
                make_float4(o[0], o[1], o[2], o[3]);
        }

        if (it < ITERS) {
            // Grid-wide barrier: bar.sync -> elected release-arrive -> spin -> bar.sync
            __syncthreads();
            if (tid == 0) {
                __threadfence();                         // release block's d stores
                atomicAdd(&g_bar, 1u);
                unsigned target = (unsigned)it * NBLK;
                while (atomicAdd(&g_bar, 0u) < target) __nanosleep(64);
                __threadfence();                         // acquire peers' d stores
            }
            __syncthreads();
        }
        src = dst;
    }
}

extern "C" void kernel_launch(void* const* d_in, const int* in_sizes, int n_in,
                              void* d_out, int out_size) {
    const float* guid   = (const float*)d_in[0];   // (B, 8, H, W)
    const float* blur   = (const float*)d_in[1];   // (B, 1, H, W)
    const float* sparse = (const float*)d_in[2];   // (B, 1, H, W)
    float* out = (float*)d_out;                    // (B, H, W)

    static bool attr_done = false;
    if (!attr_done) {
        cudaFuncSetAttribute(prop_persist,
                             cudaFuncAttributeMaxDynamicSharedMemorySize, SMEM_BYTES);
        attr_done = true;
    }

    prep_kernel<<<(BHW + 255) / 256, 256>>>(guid, blur, sparse);

    dim3 grid(W / TW, H / TH, Bn);                 // (2, 32, 2) = 128 blocks
    prop_persist<<<grid, THREADS, SMEM_BYTES>>>(blur, out);
}

// round 15
// speedup vs baseline: 1.8343x; 1.2973x over previous
#include <cuda_runtime.h>
#include <cuda_fp16.h>

#define Bn 2
#define H 384
#define W 1280
#define HW (H * W)
#define BHW (Bn * H * W)

// Persistent kernel, full-width bands: tile = 1280 x 6, grid = 64 bands x 2 batches.
#define TH 6
#define SPR (W / 4)             // strips per row = 320
#define NSTRIP (SPR * TH)       // 1920 strips per tile
#define THREADS 960             // 2 strips per thread
#define NBANDS (H / TH)         // 64
#define NBLK (NBANDS * Bn)      // 128 blocks, all co-resident (< 148 SMs, 1 blk/SM)
#define ITERS 24

#define S_W_BYTES (NSTRIP * 64)        // 122880: fp16 weights, [p][strip] layout
#define S_C_BYTES (NSTRIP * 16)        // 30720:  C as float4 per strip
#define S_D_BYTES (TH * W * 4)         // 30720:  one d buffer
#define SMEM_BYTES (S_W_BYTES + S_C_BYTES + 2 * S_D_BYTES)   // 215040

// Persistent scratch (no allocations allowed in kernel_launch).
__device__ __half   g_wh[(size_t)8 * BHW];  // fp16 weights, pixel-major [pix][k0..k7]
__device__ float    g_c[BHW];               // constant term per pixel
__device__ float    g_d0[BHW];              // publish buffer (even iters)
__device__ float    g_d1[BHW];              // publish buffer (odd iters)
__device__ unsigned g_bar;                  // grid barrier counter (reset by prep)

// Neighbor offsets per channel k (derived from PADS):
// k0:(+1,+1) k1:(+1,0) k2:(+1,-1) k3:(0,+1) k4:(0,-1) k5:(-1,+1) k6:(-1,0) k7:(-1,-1)
__constant__ int c_di[8] = { 1, 1, 1, 0, 0, -1, -1, -1 };
__constant__ int c_dj[8] = { 1, 0, -1, 1, -1, 1, 0, -1 };

__global__ void prep_kernel(const float* __restrict__ guid,
                            const float* __restrict__ blur,
                            const float* __restrict__ sparse) {
    int idx = blockIdx.x * blockDim.x + threadIdx.x;
    if (idx == 0) g_bar = 0;                 // reset grid barrier every call
    if (idx >= BHW) return;
    int j = idx % W;
    int t = idx / W;
    int i = t % H;
    int b = t / H;

    float v[8];
    float den = 0.0f;
#pragma unroll
    for (int k = 0; k < 8; k++) {
        int ni = i + c_di[k];
        int nj = j + c_dj[k];
        float val = 0.0f;
        if (ni >= 0 && ni < H && nj >= 0 && nj < W)
            val = guid[((b * 8 + k) * H + ni) * W + nj];
        v[k] = val;
        den += fabsf(val);
    }
    float inv = 1.0f / (den + 1e-9f);
    float gs = 0.0f;
#pragma unroll
    for (int k = 0; k < 8; k++) {
        v[k] *= inv;
        gs += v[k];
    }
    float m = (sparse[idx] > 0.0f) ? 1.0f : 0.0f;
    float fac = 1.0f - m;
    float raw = blur[idx];
    g_c[idx] = (fac * (1.0f - gs) + m) * raw;

    // Pack 8 fp16 weights per pixel (16B). OOB weights are exactly 0 in fp16 too.
    __half2 h0 = __floats2half2_rn(fac * v[0], fac * v[1]);
    __half2 h1 = __floats2half2_rn(fac * v[2], fac * v[3]);
    __half2 h2 = __floats2half2_rn(fac * v[4], fac * v[5]);
    __half2 h3 = __floats2half2_rn(fac * v[6], fac * v[7]);
    uint4 pack;
    pack.x = *reinterpret_cast<unsigned int*>(&h0);
    pack.y = *reinterpret_cast<unsigned int*>(&h1);
    pack.z = *reinterpret_cast<unsigned int*>(&h2);
    pack.w = *reinterpret_cast<unsigned int*>(&h3);
    *reinterpret_cast<uint4*>(g_wh + (size_t)idx * 8) = pack;
}

// Load 6 consecutive values [j0-1 .. j0+4] from a full-width row (smem or gmem).
// Col clamps at image edges are harmless: the matching weights are exactly 0.
__device__ __forceinline__ void load6(const float* __restrict__ row, int j0, float v[6]) {
    v[0] = row[(j0 > 0) ? (j0 - 1) : 0];
    float4 m = *reinterpret_cast<const float4*>(row + j0);
    v[1] = m.x; v[2] = m.y; v[3] = m.z; v[4] = m.w;
    v[5] = row[(j0 + 4 < W) ? (j0 + 4) : (W - 1)];
}

// One 4-px strip of the stencil: d_new = C + sum_k w_k * d[nbr_k].
__device__ __forceinline__ float4 calc_strip(const uint4* __restrict__ s_w,
                                             const float4* __restrict__ s_c, int st,
                                             const float* up, const float* mid,
                                             const float* dn, int j0) {
    float ru[6], rm[6], rd[6];
    load6(up,  j0, ru);
    load6(mid, j0, rm);
    load6(dn,  j0, rd);
    float4 cc = s_c[st];
    float c[4] = { cc.x, cc.y, cc.z, cc.w };
    float o[4];
#pragma unroll
    for (int p = 0; p < 4; p++) {
        uint4 wv = s_w[p * NSTRIP + st];
        __half2 h0 = *reinterpret_cast<__half2*>(&wv.x);
        __half2 h1 = *reinterpret_cast<__half2*>(&wv.y);
        __half2 h2 = *reinterpret_cast<__half2*>(&wv.z);
        __half2 h3 = *reinterpret_cast<__half2*>(&wv.w);
        float2 w01 = __half22float2(h0);   // k0, k1
        float2 w23 = __half22float2(h1);   // k2, k3
        float2 w45 = __half22float2(h2);   // k4, k5
        float2 w67 = __half22float2(h3);   // k6, k7

        float acc = c[p];
        acc = fmaf(w01.x, rd[p + 2], acc);   // (+1,+1)
        acc = fmaf(w01.y, rd[p + 1], acc);   // (+1, 0)
        acc = fmaf(w23.x, rd[p],     acc);   // (+1,-1)
        acc = fmaf(w23.y, rm[p + 2], acc);   // ( 0,+1)
        acc = fmaf(w45.x, rm[p],     acc);   // ( 0,-1)
        acc = fmaf(w45.y, ru[p + 2], acc);   // (-1,+1)
        acc = fmaf(w67.x, ru[p + 1], acc);   // (-1, 0)
        acc = fmaf(w67.y, ru[p],     acc);   // (-1,-1)
        o[p] = acc;
    }
    return make_float4(o[0], o[1], o[2], o[3]);
}

// Persistent kernel: all 24 sweeps in one launch. d lives in double-buffered SMEM;
// only the 2 boundary rows per band round-trip global memory each iteration, and
// the grid barrier is overlapped with interior compute.
__global__ __launch_bounds__(THREADS, 1)
void prop_persist(const float* __restrict__ blur, float* __restrict__ out) {
    extern __shared__ char sm[];
    uint4*  s_w  = reinterpret_cast<uint4*>(sm);
    float4* s_c  = reinterpret_cast<float4*>(sm + S_W_BYTES);
    float*  sdb0 = reinterpret_cast<float*>(sm + S_W_BYTES + S_C_BYTES);
    float*  sdb1 = reinterpret_cast<float*>(sm + S_W_BYTES + S_C_BYTES + S_D_BYTES);

    const int tid  = threadIdx.x;
    const int band = blockIdx.x;
    const int b    = blockIdx.y;
    const int ti   = band * TH;

    // ---- prologue: stage weights (transposed [p][strip]), C, and initial d.
    for (int st = tid; st < NSTRIP; st += THREADS) {
        int r = st / SPR, cq = st - r * SPR;
        int gp = (b * H + ti + r) * W + cq * 4;
        const uint4* wsrc = reinterpret_cast<const uint4*>(g_wh + (size_t)gp * 8);
#pragma unroll
        for (int p = 0; p < 4; p++) s_w[p * NSTRIP + st] = wsrc[p];
        s_c[st] = *reinterpret_cast<const float4*>(g_c + gp);
        *reinterpret_cast<float4*>(sdb0 + r * W + cq * 4) =
            *reinterpret_cast<const float4*>(blur + (size_t)(b * H + ti + r) * W + cq * 4);
    }
    __syncthreads();

    const int st0 = tid,  st1 = tid + THREADS;
    const int r0  = st0 / SPR;                       // 0..2
    const int r1  = r0 + 3;                          // 3..5
    const int j0  = (st0 - r0 * SPR) * 4;            // same column for both strips
    const bool top = (r0 == 0);
    const bool bot = (r1 == TH - 1);

    int cur = 0;
    for (int it = 1; it <= ITERS; ++it) {
        const float* sd = cur ? sdb1 : sdb0;
        float*       sn = cur ? sdb0 : sdb1;
        const bool last = (it == ITERS);
        const float* haloSrc = (it == 1) ? blur : ((it & 1) ? g_d0 : g_d1); // pub(it-1)

        // ---- phase A: interior rows (own-tile data only, no barrier needed)
        float4 o0, o1;
        if (!top) o0 = calc_strip(s_w, s_c, st0, sd + (r0 - 1) * W, sd + r0 * W,
                                  sd + (r0 + 1) * W, j0);
        if (!bot) o1 = calc_strip(s_w, s_c, st1, sd + (r1 - 1) * W, sd + r1 * W,
                                  sd + (r1 + 1) * W, j0);

        // ---- grid barrier: peers' publish of iter it-1 must be visible
        if (it > 1) {
            if (tid == 0) {
                unsigned target = (unsigned)(it - 1) * NBLK;
                volatile unsigned* vb = &g_bar;
                while (*vb < target) __nanosleep(32);
                __threadfence();                     // acquire peers' published rows
            }
            __syncthreads();
        }

        // ---- phase B: boundary rows using peers' published halo rows
        if (top) {
            const float* up = (ti == 0) ? sd                                   // image edge: w==0
                                        : haloSrc + (size_t)(b * H + ti - 1) * W;
            o0 = calc_strip(s_w, s_c, st0, up, sd, sd + W, j0);
        }
        if (bot) {
            const float* dn = (ti + TH == H) ? sd + (TH - 1) * W               // image edge: w==0
                                             : haloSrc + (size_t)(b * H + ti + TH) * W;
            o1 = calc_strip(s_w, s_c, st1, sd + (TH - 2) * W, sd + (TH - 1) * W, dn, j0);
        }

        // ---- phase C: write back
        if (last) {
            *reinterpret_cast<float4*>(out + (size_t)(b * H + ti + r0) * W + j0) = o0;
            *reinterpret_cast<float4*>(out + (size_t)(b * H + ti + r1) * W + j0) = o1;
        } else {
            *reinterpret_cast<float4*>(sn + r0 * W + j0) = o0;
            *reinterpret_cast<float4*>(sn + r1 * W + j0) = o1;
            float* pub = (it & 1) ? g_d1 : g_d0;     // pub(it)
            if (top) *reinterpret_cast<float4*>(pub + (size_t)(b * H + ti) * W + j0) = o0;
            if (bot) *reinterpret_cast<float4*>(pub + (size_t)(b * H + ti + TH - 1) * W + j0) = o1;
            __syncthreads();                          // all publishes HB tid0's fence
            if (tid == 0) {
                __threadfence();                      // release published rows
                atomicAdd(&g_bar, 1u);                // arrive
            }
        }
        cur ^= 1;
    }
}

extern "C" void kernel_launch(void* const* d_in, const int* in_sizes, int n_in,
                              void* d_out, int out_size) {
    const float* guid   = (const float*)d_in[0];   // (B, 8, H, W)
    const float* blur   = (const float*)d_in[1];   // (B, 1, H, W)
    const float* sparse = (const float*)d_in[2];   // (B, 1, H, W)
    float* out = (float*)d_out;                    // (B, H, W)

    cudaFuncSetAttribute(prop_persist,
                         cudaFuncAttributeMaxDynamicSharedMemorySize, SMEM_BYTES);

    prep_kernel<<<(BHW + 255) / 256, 256>>>(guid, blur, sparse);

    dim3 grid(NBANDS, Bn, 1);                      // (64, 2) = 128 blocks
    prop_persist<<<grid, THREADS, SMEM_BYTES>>>(blur, out);
}

// round 16
// speedup vs baseline: 2.0484x; 1.1167x over previous
#include <cuda_runtime.h>
#include <cuda_fp16.h>

#define Bn 2
#define H 384
#define W 1280
#define HW (H * W)
#define BHW (Bn * H * W)

// Persistent kernel, full-width bands: tile = 1280 x 6, grid = 64 bands x 2 batches.
// 3 layers x 2 adjacent rows per thread; d lives in registers.
#define TH 6
#define SPR (W / 4)             // strips per row = 320
#define NSTRIP (SPR * TH)       // 1920 strips per tile
#define THREADS 960             // 320 cols x 3 layers
#define NBANDS (H / TH)         // 64
#define NBLK (NBANDS * Bn)      // 128 blocks, all co-resident (< 148 SMs, 1 blk/SM)
#define ITERS 24

#define S_W_BYTES  (NSTRIP * 64)     // 122880: fp16 weights, [p][strip]
#define S_C_BYTES  (NSTRIP * 16)     // 30720:  C as float4 per strip
#define S_EDGE_FL2 (TH * SPR)        // 1920 float2 per buffer (15360 B)
#define S_IF_FL4   (4 * SPR)         // 1280 float4 per buffer (20480 B)
#define SMEM_BYTES (S_W_BYTES + S_C_BYTES + 2 * S_EDGE_FL2 * 8 + 2 * S_IF_FL4 * 16) // 225280

// Persistent scratch (no allocations allowed in kernel_launch).
__device__ __half   g_wh[(size_t)8 * BHW];  // fp16 weights, pixel-major [pix][k0..k7]
__device__ float    g_c[BHW];               // constant term per pixel
__device__ float    g_d0[BHW];              // publish buffer (odd iters)
__device__ float    g_d1[BHW];              // publish buffer (even iters)
__device__ unsigned g_bar;                  // grid barrier counter (reset by prep)

// Neighbor offsets per channel k (derived from PADS):
// k0:(+1,+1) k1:(+1,0) k2:(+1,-1) k3:(0,+1) k4:(0,-1) k5:(-1,+1) k6:(-1,0) k7:(-1,-1)
__constant__ int c_di[8] = { 1, 1, 1, 0, 0, -1, -1, -1 };
__constant__ int c_dj[8] = { 1, 0, -1, 1, -1, 1, 0, -1 };

__global__ void prep_kernel(const float* __restrict__ guid,
                            const float* __restrict__ blur,
                            const float* __restrict__ sparse) {
    int idx = blockIdx.x * blockDim.x + threadIdx.x;
    if (idx == 0) g_bar = 0;                 // reset grid barrier every call
    if (idx >= BHW) return;
    int j = idx % W;
    int t = idx / W;
    int i = t % H;
    int b = t / H;

    float v[8];
    float den = 0.0f;
#pragma unroll
    for (int k = 0; k < 8; k++) {
        int ni = i + c_di[k];
        int nj = j + c_dj[k];
        float val = 0.0f;
        if (ni >= 0 && ni < H && nj >= 0 && nj < W)
            val = guid[((b * 8 + k) * H + ni) * W + nj];
        v[k] = val;
        den += fabsf(val);
    }
    float inv = 1.0f / (den + 1e-9f);
    float gs = 0.0f;
#pragma unroll
    for (int k = 0; k < 8; k++) {
        v[k] *= inv;
        gs += v[k];
    }
    float m = (sparse[idx] > 0.0f) ? 1.0f : 0.0f;
    float fac = 1.0f - m;
    float raw = blur[idx];
    g_c[idx] = (fac * (1.0f - gs) + m) * raw;

    // Pack 8 fp16 weights per pixel (16B). OOB weights are exactly 0 in fp16 too.
    __half2 h0 = __floats2half2_rn(fac * v[0], fac * v[1]);
    __half2 h1 = __floats2half2_rn(fac * v[2], fac * v[3]);
    __half2 h2 = __floats2half2_rn(fac * v[4], fac * v[5]);
    __half2 h3 = __floats2half2_rn(fac * v[6], fac * v[7]);
    uint4 pack;
    pack.x = *reinterpret_cast<unsigned int*>(&h0);
    pack.y = *reinterpret_cast<unsigned int*>(&h1);
    pack.z = *reinterpret_cast<unsigned int*>(&h2);
    pack.w = *reinterpret_cast<unsigned int*>(&h3);
    *reinterpret_cast<uint4*>(g_wh + (size_t)idx * 8) = pack;
}

// Stencil for one 4-px row strip from prebuilt 6-wide rows.
// up/mi/dn = {col j0-1, j0..j0+3, j0+4} of rows r-1, r, r+1.
__device__ __forceinline__ float4 row_calc(const uint4* __restrict__ s_w,
                                           const float4* __restrict__ s_c, int st,
                                           const float* up, const float* mi,
                                           const float* dn) {
    float4 cc = s_c[st];
    float cv[4] = { cc.x, cc.y, cc.z, cc.w };
    float o[4];
#pragma unroll
    for (int p = 0; p < 4; p++) {
        uint4 wv = s_w[p * NSTRIP + st];
        __half2 h0 = *reinterpret_cast<__half2*>(&wv.x);
        __half2 h1 = *reinterpret_cast<__half2*>(&wv.y);
        __half2 h2 = *reinterpret_cast<__half2*>(&wv.z);
        __half2 h3 = *reinterpret_cast<__half2*>(&wv.w);
        float2 w01 = __half22float2(h0);   // k0, k1
        float2 w23 = __half22float2(h1);   // k2, k3
        float2 w45 = __half22float2(h2);   // k4, k5
        float2 w67 = __half22float2(h3);   // k6, k7

        float acc = cv[p];
        acc = fmaf(w01.x, dn[p + 2], acc);   // (+1,+1)
        acc = fmaf(w01.y, dn[p + 1], acc);   // (+1, 0)
        acc = fmaf(w23.x, dn[p],     acc);   // (+1,-1)
        acc = fmaf(w23.y, mi[p + 2], acc);   // ( 0,+1)
        acc = fmaf(w45.x, mi[p],     acc);   // ( 0,-1)
        acc = fmaf(w45.y, up[p + 2], acc);   // (-1,+1)
        acc = fmaf(w67.x, up[p + 1], acc);   // (-1, 0)
        acc = fmaf(w67.y, up[p],     acc);   // (-1,-1)
        o[p] = acc;
    }
    return make_float4(o[0], o[1], o[2], o[3]);
}

__device__ __forceinline__ void halo6(const float* __restrict__ hrow, int j0, float v[6]) {
    v[0] = hrow[(j0 > 0) ? (j0 - 1) : 0];
    float4 h = *reinterpret_cast<const float4*>(hrow + j0);
    v[1] = h.x; v[2] = h.y; v[3] = h.z; v[4] = h.w;
    v[5] = hrow[(j0 + 4 < W) ? (j0 + 4) : (W - 1)];
}

// Persistent kernel: 24 sweeps in one launch. Each thread keeps its 2 adjacent rows
// (8 px) in registers; smem carries only weights, C, per-row edge columns, and the
// 4 interface rows (rows 1-4), double-buffered by iteration parity.
__global__ __launch_bounds__(THREADS, 1)
void prop_persist(const float* __restrict__ blur, float* __restrict__ out) {
    extern __shared__ char sm[];
    uint4*  s_w    = reinterpret_cast<uint4*>(sm);
    float4* s_c    = reinterpret_cast<float4*>(sm + S_W_BYTES);
    float2* s_edge = reinterpret_cast<float2*>(sm + S_W_BYTES + S_C_BYTES);            // [2][TH][SPR]
    float4* s_if   = reinterpret_cast<float4*>(sm + S_W_BYTES + S_C_BYTES
                                               + 2 * S_EDGE_FL2 * 8);                  // [2][4][SPR]

    const int tid  = threadIdx.x;
    const int rp   = tid / SPR;                  // layer 0..2
    const int c    = tid - rp * SPR;             // column strip 0..319
    const int j0   = c * 4;
    const int band = blockIdx.x;
    const int b    = blockIdx.y;
    const int ti   = band * TH;
    const int ra   = 2 * rp, rb = ra + 1;        // owned rows within band
    const int cm   = (c > 0) ? c - 1 : 0;        // clamped neighbors (image edge: w==0)
    const int cp   = (c < SPR - 1) ? c + 1 : SPR - 1;

    // ---- prologue: stage weights (transposed [p][strip]) + C
    for (int st = tid; st < NSTRIP; st += THREADS) {
        int r = st / SPR, cq = st - r * SPR;
        int gp = (b * H + ti + r) * W + cq * 4;
        const uint4* wsrc = reinterpret_cast<const uint4*>(g_wh + (size_t)gp * 8);
#pragma unroll
        for (int p = 0; p < 4; p++) s_w[p * NSTRIP + st] = wsrc[p];
        s_c[st] = *reinterpret_cast<const float4*>(g_c + gp);
    }
    // own rows into registers, initial edge/iface into buffer 0
    float4 dA = *reinterpret_cast<const float4*>(blur + (size_t)(b * H + ti + ra) * W + j0);
    float4 dB = *reinterpret_cast<const float4*>(blur + (size_t)(b * H + ti + rb) * W + j0);
    s_edge[ra * SPR + c] = make_float2(dA.x, dA.w);
    s_edge[rb * SPR + c] = make_float2(dB.x, dB.w);
    if (rp == 0)      { s_if[0 * SPR + c] = dB; }                          // row 1
    else if (rp == 1) { s_if[1 * SPR + c] = dA; s_if[2 * SPR + c] = dB; }  // rows 2,3
    else              { s_if[3 * SPR + c] = dA; }                          // row 4
    __syncthreads();

    for (int it = 1; it <= ITERS; ++it) {
        const int rd = (it - 1) & 1, wr = it & 1;
        const float2* eg = s_edge + rd * S_EDGE_FL2;
        const float4* fc = s_if   + rd * S_IF_FL4;
        const bool last = (it == ITERS);
        const float* haloSrc = (it == 1) ? blur : ((it & 1) ? g_d0 : g_d1);  // pub(it-1)

        // own rows as 6-wide arrays (edges from smem)
        float a6[6] = { eg[ra * SPR + cm].y, dA.x, dA.y, dA.z, dA.w, eg[ra * SPR + cp].x };
        float b6[6] = { eg[rb * SPR + cm].y, dB.x, dB.y, dB.z, dB.w, eg[rb * SPR + cp].x };

        float4 nA, nB;

        // ---- phase A: rows 1..4 (no grid dependency)
        if (rp == 0) {
            float4 f = fc[1 * SPR + c];                                    // row 2
            float d6[6] = { eg[2 * SPR + cm].y, f.x, f.y, f.z, f.w, eg[2 * SPR + cp].x };
            nB = row_calc(s_w, s_c, 1 * SPR + c, a6, b6, d6);              // row 1
        } else if (rp == 1) {
            float4 f1 = fc[0 * SPR + c];                                   // row 1
            float u6[6] = { eg[1 * SPR + cm].y, f1.x, f1.y, f1.z, f1.w, eg[1 * SPR + cp].x };
            nA = row_calc(s_w, s_c, 2 * SPR + c, u6, a6, b6);              // row 2
            float4 f4 = fc[3 * SPR + c];                                   // row 4
            float d6[6] = { eg[4 * SPR + cm].y, f4.x, f4.y, f4.z, f4.w, eg[4 * SPR + cp].x };
            nB = row_calc(s_w, s_c, 3 * SPR + c, a6, b6, d6);              // row 3
        } else {
            float4 f3 = fc[2 * SPR + c];                                   // row 3
            float u6[6] = { eg[3 * SPR + cm].y, f3.x, f3.y, f3.z, f3.w, eg[3 * SPR + cp].x };
            nA = row_calc(s_w, s_c, 4 * SPR + c, u6, a6, b6);              // row 4
        }

        // ---- grid barrier: publishes of it-1 must be visible
        if (it > 1) {
            if (tid == 0) {
                unsigned target = (unsigned)(it - 1) * NBLK;
                volatile unsigned* vb = &g_bar;
                while (*vb < target) __nanosleep(32);
                __threadfence();                 // acquire peers' published rows
            }
            __syncthreads();
        }

        // ---- phase B: boundary rows 0 and 5 using peers' published halo rows
        if (rp == 0) {
            float u6[6];
            if (ti == 0) {                        // image top: up-weights are 0
#pragma unroll
                for (int q = 0; q < 6; q++) u6[q] = a6[q];
            } else {
                halo6(haloSrc + (size_t)(b * H + ti - 1) * W, j0, u6);
            }
            nA = row_calc(s_w, s_c, 0 * SPR + c, u6, a6, b6);              // row 0
        } else if (rp == 2) {
            float d6[6];
            if (ti + TH == H) {                   // image bottom: down-weights are 0
#pragma unroll
                for (int q = 0; q < 6; q++) d6[q] = b6[q];
            } else {
                halo6(haloSrc + (size_t)(b * H + ti + TH) * W, j0, d6);
            }
            nB = row_calc(s_w, s_c, 5 * SPR + c, a6, b6, d6);              // row 5
        }

        // ---- write back
        if (last) {
            *reinterpret_cast<float4*>(out + (size_t)(b * H + ti + ra) * W + j0) = nA;
            *reinterpret_cast<float4*>(out + (size_t)(b * H + ti + rb) * W + j0) = nB;
        } else {
            float* pub = (it & 1) ? g_d1 : g_d0;  // pub(it)
            if (rp == 0)
                *reinterpret_cast<float4*>(pub + (size_t)(b * H + ti) * W + j0) = nA;
            if (rp == 2)
                *reinterpret_cast<float4*>(pub + (size_t)(b * H + ti + TH - 1) * W + j0) = nB;

            float2* egw = s_edge + wr * S_EDGE_FL2;
            float4* fcw = s_if   + wr * S_IF_FL4;
            egw[ra * SPR + c] = make_float2(nA.x, nA.w);
            egw[rb * SPR + c] = make_float2(nB.x, nB.w);
            if (rp == 0)      { fcw[0 * SPR + c] = nB; }
            else if (rp == 1) { fcw[1 * SPR + c] = nA; fcw[2 * SPR + c] = nB; }
            else              { fcw[3 * SPR + c] = nA; }

            __syncthreads();                      // publishes + smem writes done
            if (tid == 0) {
                __threadfence();                  // release published rows
                atomicAdd(&g_bar, 1u);            // arrive
            }
            dA = nA; dB = nB;
        }
    }
}

extern "C" void kernel_launch(void* const* d_in, const int* in_sizes, int n_in,
                              void* d_out, int out_size) {
    const float* guid   = (const float*)d_in[0];   // (B, 8, H, W)
    const float* blur   = (const float*)d_in[1];   // (B, 1, H, W)
    const float* sparse = (const float*)d_in[2];   // (B, 1, H, W)
    float* out = (float*)d_out;                    // (B, H, W)

    cudaFuncSetAttribute(prop_persist,
                         cudaFuncAttributeMaxDynamicSharedMemorySize, SMEM_BYTES);

    prep_kernel<<<(BHW + 255) / 256, 256>>>(guid, blur, sparse);

    dim3 grid(NBANDS, Bn, 1);                      // (64, 2) = 128 blocks
    prop_persist<<<grid, THREADS, SMEM_BYTES>>>(blur, out);
}